// round 12
// baseline (speedup 1.0000x reference)
#include <cuda_runtime.h>
#include <cuda_bf16.h>

// embeddings [B=512, I=128, D=64] fp32
// out[b,i,d] = tanh( emb[b,i,d] * (1/I) * sum_j emb[b,j,d] )
//
// R12: R2's exact memory shape (f4-col c=t&7 -> warp-LDG covers 4 full
// 128B lines) but QUARTER-SIZE CTAs: 1024 CTAs x 128 threads (4 warps).
// Thread t: rows rg+16k, 8 independent LDG.128 (MLP 8). Shuffle xor(8,16)
// -> 4 warp partials -> ONE 4-warp barrier -> per-thread redundant final
// over 4 partials (4 broadcast LDS + 3 adds; no serialized thread, no
// second barrier). Halves barrier scope & arrival skew vs R2.

static constexpr int BATCH   = 512;
static constexpr int SEQ_I   = 128;
static constexpr int F4_ROW  = 16;       // 64 floats / 4
static constexpr int F4_COLS = 8;        // f4 columns per CTA chunk
static constexpr int THREADS = 128;

__device__ __forceinline__ float fast_tanh(float x) {
    float y;
    asm("tanh.approx.f32 %0, %1;" : "=f"(y) : "f"(x));
    return y;
}

__global__ __launch_bounds__(THREADS, 16)
void ATT0_40707700032104_kernel(const float4* __restrict__ in,
                                float4* __restrict__ out) {
    const int b    = blockIdx.x >> 1;
    const int half = blockIdx.x & 1;
    const int t    = threadIdx.x;
    const int c    = t & (F4_COLS - 1);   // f4 column in chunk (0..7)
    const int rg   = t >> 3;              // base row (0..15)
    const int lane = t & 31;
    const int w    = t >> 5;              // warp id (0..3)

    const size_t base = (size_t)b * (SEQ_I * F4_ROW) + half * F4_COLS + c;
    const float4* src = in  + base;
    float4*       dst = out + base;

    // ---- 8 independent coalesced LDG.128 (rows rg + 16k), kept in regs ----
    float4 v[8];
#pragma unroll
    for (int k = 0; k < 8; k++)
        v[k] = src[(size_t)(rg + 16 * k) * F4_ROW];

    float4 s;
    s.x = ((v[0].x + v[1].x) + (v[2].x + v[3].x)) + ((v[4].x + v[5].x) + (v[6].x + v[7].x));
    s.y = ((v[0].y + v[1].y) + (v[2].y + v[3].y)) + ((v[4].y + v[5].y) + (v[6].y + v[7].y));
    s.z = ((v[0].z + v[1].z) + (v[2].z + v[3].z)) + ((v[4].z + v[5].z) + (v[6].z + v[7].z));
    s.w = ((v[0].w + v[1].w) + (v[2].w + v[3].w)) + ((v[4].w + v[5].w) + (v[6].w + v[7].w));

    // ---- Warp reduce: lanes l, l+8, l+16, l+24 share column c ----
#pragma unroll
    for (int off = 8; off <= 16; off <<= 1) {
        s.x += __shfl_xor_sync(0xffffffffu, s.x, off);
        s.y += __shfl_xor_sync(0xffffffffu, s.y, off);
        s.z += __shfl_xor_sync(0xffffffffu, s.z, off);
        s.w += __shfl_xor_sync(0xffffffffu, s.w, off);
    }

    // ---- Publish 4 warp partials; ONE 4-warp barrier ----
    __shared__ float4 wsum[4][F4_COLS];
    if (lane < F4_COLS) wsum[w][lane] = s;
    __syncthreads();

    // ---- Redundant per-thread final: 4 broadcast LDS.128 + 3 adds ----
    float4 p0 = wsum[0][c], p1 = wsum[1][c], p2 = wsum[2][c], p3 = wsum[3][c];
    const float inv = 1.0f / (float)SEQ_I;
    float4 m;
    m.x = ((p0.x + p1.x) + (p2.x + p3.x)) * inv;
    m.y = ((p0.y + p1.y) + (p2.y + p3.y)) * inv;
    m.z = ((p0.z + p1.z) + (p2.z + p3.z)) * inv;
    m.w = ((p0.w + p1.w) + (p2.w + p3.w)) * inv;

    // ---- tanh(v * mean) from registers, 8 coalesced STG.128 ----
#pragma unroll
    for (int k = 0; k < 8; k++) {
        float4 r;
        r.x = fast_tanh(v[k].x * m.x);
        r.y = fast_tanh(v[k].y * m.y);
        r.z = fast_tanh(v[k].z * m.z);
        r.w = fast_tanh(v[k].w * m.w);
        dst[(size_t)(rg + 16 * k) * F4_ROW] = r;
    }
}

extern "C" void kernel_launch(void* const* d_in, const int* in_sizes, int n_in,
                              void* d_out, int out_size) {
    const float4* in  = (const float4*)d_in[0];
    float4*       out = (float4*)d_out;
    ATT0_40707700032104_kernel<<<BATCH * 2, THREADS>>>(in, out);
}

// round 13
// speedup vs baseline: 1.2989x; 1.2989x over previous
#include <cuda_runtime.h>
#include <cuda_bf16.h>

// embeddings [B=512, I=128, D=64] fp32
// out[b,i,d] = tanh( emb[b,i,d] * (1/I) * sum_j emb[b,j,d] )
//
// R13 = exact R2 (best of 13 structural variants, 8.672us): lock-in +
// reproducibility verification. Why this shape won every comparison:
//  - f4-col c=t&7 lane layout -> each warp-LDG covers 4 FULL 128B lines
//    (R8/R12 deviations paid 1.5-2x on the load path);
//  - 4 float4 per thread fits the 32-reg sweet spot, truly reg-resident
//    (R11/R12 bigger buffers were silently demoted by ptxas);
//  - 1024 CTAs x 256 thr = single wave at ~8 CTA/SM (R10 multi-wave and
//    R4 two-pass paid transition/launch costs);
//  - shuffle xor(8,16) + 8x8 smem stage + 8-thread final: cheapest
//    measured reduce (R5/R8 redundant/barrier-free variants were worse).
// All throughput units <=30% in every profile; remaining time is fixed
// replay overhead + one DRAM-roundtrip latency chain.

static constexpr int BATCH   = 512;
static constexpr int SEQ_I   = 128;
static constexpr int F4_ROW  = 16;      // 64 floats / 4
static constexpr int F4_COLS = 8;       // f4 columns per CTA chunk
static constexpr int THREADS = 256;

__device__ __forceinline__ float fast_tanh(float x) {
    float y;
    asm("tanh.approx.f32 %0, %1;" : "=f"(y) : "f"(x));
    return y;
}

__global__ __launch_bounds__(THREADS, 8)
void ATT0_40707700032104_kernel(const float4* __restrict__ in,
                                float4* __restrict__ out) {
    const int b    = blockIdx.x >> 1;
    const int half = blockIdx.x & 1;
    const int t    = threadIdx.x;
    const int c    = t & (F4_COLS - 1);   // f4 column in chunk (0..7)
    const int rg   = t >> 3;              // base row (0..31)
    const int lane = t & 31;
    const int w    = t >> 5;              // warp id (0..7)

    const size_t base = (size_t)b * (SEQ_I * F4_ROW) + half * F4_COLS + c;
    const float4* src = in  + base;
    float4*       dst = out + base;

    // ---- 4 independent coalesced LDG.128 (rows rg + 32k), kept in regs ----
    float4 v[4];
#pragma unroll
    for (int k = 0; k < 4; k++)
        v[k] = src[(size_t)(rg + 32 * k) * F4_ROW];

    float4 s;
    s.x = (v[0].x + v[1].x) + (v[2].x + v[3].x);
    s.y = (v[0].y + v[1].y) + (v[2].y + v[3].y);
    s.z = (v[0].z + v[1].z) + (v[2].z + v[3].z);
    s.w = (v[0].w + v[1].w) + (v[2].w + v[3].w);

    // ---- Warp reduce: lanes l, l+8, l+16, l+24 share column c ----
#pragma unroll
    for (int off = 8; off <= 16; off <<= 1) {
        s.x += __shfl_xor_sync(0xffffffffu, s.x, off);
        s.y += __shfl_xor_sync(0xffffffffu, s.y, off);
        s.z += __shfl_xor_sync(0xffffffffu, s.z, off);
        s.w += __shfl_xor_sync(0xffffffffu, s.w, off);
    }

    // ---- Cross-warp reduce via 8x8 smem stage ----
    __shared__ float4 wsum[8][F4_COLS];
    __shared__ float4 mean4[F4_COLS];
    if (lane < F4_COLS) wsum[w][lane] = s;
    __syncthreads();

    if (t < F4_COLS) {
        float4 m = wsum[0][t];
#pragma unroll
        for (int ww = 1; ww < 8; ww++) {
            float4 p = wsum[ww][t];
            m.x += p.x; m.y += p.y; m.z += p.z; m.w += p.w;
        }
        const float inv = 1.0f / (float)SEQ_I;
        m.x *= inv; m.y *= inv; m.z *= inv; m.w *= inv;
        mean4[t] = m;
    }
    __syncthreads();

    const float4 m = mean4[c];

    // ---- tanh(v * mean) from registers, 4 coalesced STG.128 ----
#pragma unroll
    for (int k = 0; k < 4; k++) {
        float4 r;
        r.x = fast_tanh(v[k].x * m.x);
        r.y = fast_tanh(v[k].y * m.y);
        r.z = fast_tanh(v[k].z * m.z);
        r.w = fast_tanh(v[k].w * m.w);
        dst[(size_t)(rg + 32 * k) * F4_ROW] = r;
    }
}

extern "C" void kernel_launch(void* const* d_in, const int* in_sizes, int n_in,
                              void* d_out, int out_size) {
    const float4* in  = (const float4*)d_in[0];
    float4*       out = (float4*)d_out;
    ATT0_40707700032104_kernel<<<BATCH * 2, THREADS>>>(in, out);
}